// round 1
// baseline (speedup 1.0000x reference)
#include <cuda_runtime.h>

// FindPeaks: 3x3 zero-padded neighborhood peak detection with unfold/argmax
// tie-breaking (center = kernel index 4, first-occurrence argmax):
//   peak  <=>  n0<c && n1<c && n2<c && n3<c && c>=n5 && c>=n6 && c>=n7 && c>=n8
// out = peak ? c : 0
//
// Layout: [B, 1, H, W] float32, H=W=768. Memory-bound stencil.
// One thread per float4 of output: 3 coalesced float4 loads + halo scalars (L1).

static constexpr int H = 768;
static constexpr int W = 768;

__global__ __launch_bounds__(256) void find_peaks_kernel(
    const float* __restrict__ in, float* __restrict__ out, int n_img)
{
    const int W4 = W / 4;
    int idx = blockIdx.x * blockDim.x + threadIdx.x;
    int total4 = n_img * H * W4;
    if (idx >= total4) return;

    int x4 = (idx % W4) * 4;
    int t  = idx / W4;
    int y  = t % H;
    int b  = t / H;

    const float* img = in + (size_t)b * H * W;

    // rows y-1, y, y+1; columns x4-1 .. x4+4 (6 values each), zero-padded.
    float r0[6], r1[6], r2[6];

    const bool has_top = (y > 0);
    const bool has_bot = (y < H - 1);
    const bool has_l   = (x4 > 0);
    const bool has_r   = (x4 + 4 < W);

    // center row (always valid)
    {
        const float* rp = img + (size_t)y * W;
        float4 v = *reinterpret_cast<const float4*>(rp + x4);
        r1[1] = v.x; r1[2] = v.y; r1[3] = v.z; r1[4] = v.w;
        r1[0] = has_l ? rp[x4 - 1] : 0.0f;
        r1[5] = has_r ? rp[x4 + 4] : 0.0f;
    }
    if (has_top) {
        const float* rp = img + (size_t)(y - 1) * W;
        float4 v = *reinterpret_cast<const float4*>(rp + x4);
        r0[1] = v.x; r0[2] = v.y; r0[3] = v.z; r0[4] = v.w;
        r0[0] = has_l ? rp[x4 - 1] : 0.0f;
        r0[5] = has_r ? rp[x4 + 4] : 0.0f;
    } else {
        #pragma unroll
        for (int i = 0; i < 6; i++) r0[i] = 0.0f;
    }
    if (has_bot) {
        const float* rp = img + (size_t)(y + 1) * W;
        float4 v = *reinterpret_cast<const float4*>(rp + x4);
        r2[1] = v.x; r2[2] = v.y; r2[3] = v.z; r2[4] = v.w;
        r2[0] = has_l ? rp[x4 - 1] : 0.0f;
        r2[5] = has_r ? rp[x4 + 4] : 0.0f;
    } else {
        #pragma unroll
        for (int i = 0; i < 6; i++) r2[i] = 0.0f;
    }

    float4 o;
    float* op = &o.x;
    #pragma unroll
    for (int i = 0; i < 4; i++) {
        float c = r1[i + 1];
        // kernel indices 0..3 must be strictly < c (first-occurrence argmax),
        // indices 5..8 must be <= c.
        bool peak = (r0[i]     < c) & (r0[i + 1] < c) & (r0[i + 2] < c)
                  & (r1[i]     < c)
                  & (r1[i + 2] <= c)
                  & (r2[i]     <= c) & (r2[i + 1] <= c) & (r2[i + 2] <= c);
        op[i] = peak ? c : 0.0f;
    }

    *reinterpret_cast<float4*>(out + (size_t)b * H * W + (size_t)y * W + x4) = o;
}

extern "C" void kernel_launch(void* const* d_in, const int* in_sizes, int n_in,
                              void* d_out, int out_size)
{
    const float* in = (const float*)d_in[0];
    float* out = (float*)d_out;
    int n_img = in_sizes[0] / (H * W);   // C==1
    int total4 = n_img * H * (W / 4);
    int block = 256;
    int grid = (total4 + block - 1) / block;
    find_peaks_kernel<<<grid, block>>>(in, out, n_img);
}